// round 6
// baseline (speedup 1.0000x reference)
#include <cuda_runtime.h>
#include <cuda_bf16.h>
#include <cstdint>

// Problem constants
#define NN      64          // nodes
#define TT      512         // time steps
#define BB      64          // batch
#define PP      32          // window
#define KDIM    4096        // N*N
#define NCOLS   512         // T

// ---------------------------------------------------------------------------
// Device scratch (static — allocation-free per harness rules)
// ---------------------------------------------------------------------------
__device__ float g_w[TT * KDIM];                       // softmaxed adjacency, 8 MB
__device__ __nv_bfloat16 w2t_hi[(size_t)NCOLS * KDIM]; // weights^2 transposed, 4 MB
__device__ __nv_bfloat16 w2t_lo[(size_t)NCOLS * KDIM]; // 4 MB

// ---------------------------------------------------------------------------
// PTX helpers (baseline PTX, valid on plain sm_103 target)
// ---------------------------------------------------------------------------
__device__ __forceinline__ uint32_t smem_u32(const void* p) {
    uint32_t a;
    asm("{ .reg .u64 t; cvta.to.shared.u64 t, %1; cvt.u32.u64 %0, t; }"
        : "=r"(a) : "l"(p));
    return a;
}

__device__ __forceinline__ void cp16(uint32_t dst, const void* src) {
    asm volatile("cp.async.cg.shared.global [%0], [%1], 16;"
                 :: "r"(dst), "l"(src));
}

#define CP_COMMIT() asm volatile("cp.async.commit_group;" ::: "memory")
#define CP_WAIT1()  asm volatile("cp.async.wait_group 1;"  ::: "memory")

#define LDSM4(r, addr)                                                         \
    asm volatile("ldmatrix.sync.aligned.m8n8.x4.shared.b16 "                   \
                 "{%0,%1,%2,%3}, [%4];"                                        \
                 : "=r"((r)[0]), "=r"((r)[1]), "=r"((r)[2]), "=r"((r)[3])      \
                 : "r"(addr))

#define MMA16816(c, a, b0, b1)                                                 \
    asm volatile("mma.sync.aligned.m16n8k16.row.col.f32.bf16.bf16.f32 "        \
                 "{%0,%1,%2,%3},{%4,%5,%6,%7},{%8,%9},{%0,%1,%2,%3};"          \
                 : "+f"((c)[0]), "+f"((c)[1]), "+f"((c)[2]), "+f"((c)[3])      \
                 : "r"((a)[0]), "r"((a)[1]), "r"((a)[2]), "r"((a)[3]),         \
                   "r"(b0), "r"(b1))

__device__ __forceinline__ uint32_t pk_hi(float x, float y) {
    return ((uint32_t)__bfloat16_as_ushort(__float2bfloat16(y)) << 16) |
           __bfloat16_as_ushort(__float2bfloat16(x));
}
__device__ __forceinline__ uint32_t pk_lo(float x, float y) {
    const float lx = x - __bfloat162float(__float2bfloat16(x));
    const float ly = y - __bfloat162float(__float2bfloat16(y));
    return pk_hi(lx, ly);
}
__device__ __forceinline__ void pack8(const float4& u, const float4& v,
                                      uint4& h, uint4& l) {
    h.x = pk_hi(u.x, u.y); h.y = pk_hi(u.z, u.w);
    h.z = pk_hi(v.x, v.y); h.w = pk_hi(v.z, v.w);
    l.x = pk_lo(u.x, u.y); l.y = pk_lo(u.z, u.w);
    l.z = pk_lo(v.x, v.y); l.w = pk_lo(v.z, v.w);
}

// ---------------------------------------------------------------------------
// Kernel 0: weights -> weights^2, transposed to [T=512, K=4096], bf16 hi/lo
// ---------------------------------------------------------------------------
__global__ __launch_bounds__(256, 4)
void split_w_kernel(const float* __restrict__ w) {
    __shared__ float tile[32][33];
    const int kb = blockIdx.x;
    const int nb = blockIdx.y;
    const int tx = threadIdx.x & 31;
    const int ty = threadIdx.x >> 5;
#pragma unroll
    for (int r = 0; r < 4; r++) {
        const int k = kb * 32 + ty + r * 8;
        const float v = w[(size_t)k * NCOLS + nb * 32 + tx];
        tile[ty + r * 8][tx] = v * v;
    }
    __syncthreads();
#pragma unroll
    for (int r = 0; r < 4; r++) {
        const int n = nb * 32 + ty + r * 8;
        const int k = kb * 32 + tx;
        const float val = tile[tx][ty + r * 8];
        const __nv_bfloat16 h = __float2bfloat16(val);
        const __nv_bfloat16 l = __float2bfloat16(val - __bfloat162float(h));
        w2t_hi[(size_t)n * KDIM + k] = h;
        w2t_lo[(size_t)n * KDIM + k] = l;
    }
}

// ---------------------------------------------------------------------------
// Kernel 1: F = g @ weights^2 via mma.sync bf16 hi/lo split (fused A convert).
//   CTA tile 128x128, 256 threads = 8 warps (2 M x 4 N), warp tile 64x32.
//   3-stage pipeline, K-chunk 64.
//   A: fp32 g -> LDG regs (1 stage ahead) -> bf16 hi/lo pack -> STS (mid-stage)
//   B: bf16 hi/lo via cp.async, issued 2 stages ahead (wait_group 1)
//   Stage layout: Ahi | Alo | Bhi | Blo, each [128 x 64] bf16 SW128-swizzled.
// ---------------------------------------------------------------------------
#define TILE_BYTES  16384
#define STAGE_BYTES (4 * TILE_BYTES)      // 64 KB
#define NSTAGE      3
#define SMEM_TOTAL  (NSTAGE * STAGE_BYTES)  // 192 KB
#define KSTAGES     64

__global__ __launch_bounds__(256, 1)
void mma_gemm_kernel(const float* __restrict__ g, float* __restrict__ F) {
    extern __shared__ char smem[];
    const uint32_t sb = smem_u32(smem);
    const int tid  = threadIdx.x;
    const int lane = tid & 31;
    const int wid  = tid >> 5;
    const int bn = blockIdx.x;            // 0..3   (128-col tiles of T)
    const int bm = blockIdx.y;            // 0..31  (128-row tiles of N*N)
    const int wm = wid >> 2;              // 0..1 -> row offset wm*64
    const int wn = wid & 3;               // 0..3 -> col offset wn*32

    const float*         Ag = g      + (size_t)(bm * 128) * KDIM;
    const __nv_bfloat16* Bh = w2t_hi + (size_t)(bn * 128) * KDIM;
    const __nv_bfloat16* Bl = w2t_lo + (size_t)(bn * 128) * KDIM;

    float c[4][4][4];
#pragma unroll
    for (int mt = 0; mt < 4; mt++)
#pragma unroll
        for (int nt = 0; nt < 4; nt++)
#pragma unroll
            for (int q = 0; q < 4; q++) c[mt][nt][q] = 0.f;

    // ---- B stage issuer: 8 cp16 (Bhi + Blo) ----
    auto issue_B = [&](int s2) {
        const uint32_t bb = sb + (s2 % NSTAGE) * STAGE_BYTES + 2 * TILE_BYTES;
        const size_t ko = (size_t)s2 * 64;
#pragma unroll
        for (int j = 0; j < 4; j++) {
            const int gid = tid + j * 256;
            const int row = gid >> 3, c8 = gid & 7;
            uint32_t off = (uint32_t)(row * 128 + c8 * 16);
            off ^= (off >> 3) & 0x70;
            const size_t gi = (size_t)row * KDIM + ko + c8 * 8;
            cp16(bb + off,              Bh + gi);
            cp16(bb + TILE_BYTES + off, Bl + gi);
        }
    };

    // ---- A LDG (fp32, 8 float4) for stage s2 ----
    auto load_A = [&](int s2, float4* ar) {
        const float* Ags = Ag + s2 * 64;
#pragma unroll
        for (int j = 0; j < 4; j++) {
            const int gid = tid + j * 256;
            const int row = gid >> 3, c8 = gid & 7;
            const float* p = Ags + (size_t)row * KDIM + c8 * 8;
            ar[j * 2]     = *(const float4*)p;
            ar[j * 2 + 1] = *(const float4*)(p + 4);
        }
    };

    // ---- A convert + STS into stage s2's buffers ----
    auto store_A = [&](int s2, const float4* ar) {
        char* ab = smem + (s2 % NSTAGE) * STAGE_BYTES;
#pragma unroll
        for (int j = 0; j < 4; j++) {
            const int gid = tid + j * 256;
            const int row = gid >> 3, c8 = gid & 7;
            uint32_t off = (uint32_t)(row * 128 + c8 * 16);
            off ^= (off >> 3) & 0x70;
            uint4 h, l;
            pack8(ar[j * 2], ar[j * 2 + 1], h, l);
            *(uint4*)(ab + off)              = h;
            *(uint4*)(ab + TILE_BYTES + off) = l;
        }
    };

    const int rA = lane & 15;
    const int kHalf = (lane >> 4) << 4;

    // ---- one K=16 compute step on stage buffers ----
    auto compute_kk = [&](uint32_t ab, uint32_t al, uint32_t bh, uint32_t bl,
                          int kk) {
        const int kb = kk * 32 + kHalf;
        uint32_t ahr[4][4], alr[4][4];
#pragma unroll
        for (int mt = 0; mt < 4; mt++) {
            const int row = wm * 64 + mt * 16 + rA;
            uint32_t off = (uint32_t)(row * 128 + kb);
            off ^= (off >> 3) & 0x70;
            LDSM4(ahr[mt], ab + off);
            LDSM4(alr[mt], al + off);
        }
        uint32_t bhr[2][4], blr[2][4];
#pragma unroll
        for (int gg = 0; gg < 2; gg++) {
            const int row = wn * 32 + gg * 16 + rA;
            uint32_t off = (uint32_t)(row * 128 + kb);
            off ^= (off >> 3) & 0x70;
            LDSM4(bhr[gg], bh + off);
            LDSM4(blr[gg], bl + off);
        }
#pragma unroll
        for (int mt = 0; mt < 4; mt++)
#pragma unroll
            for (int nt = 0; nt < 4; nt++) {
                const int gg = nt >> 1, h = nt & 1;
                MMA16816(c[mt][nt], ahr[mt], bhr[gg][h], bhr[gg][h + 2]);
                MMA16816(c[mt][nt], ahr[mt], blr[gg][h], blr[gg][h + 2]);
                MMA16816(c[mt][nt], alr[mt], bhr[gg][h], bhr[gg][h + 2]);
            }
    };

    // ---- prologue: A(0) in smem, B(0) and B(1) in flight ----
    {
        float4 ar0[8];
        load_A(0, ar0);
        store_A(0, ar0);
        issue_B(0); CP_COMMIT();
        issue_B(1); CP_COMMIT();
    }

    for (int s = 0; s < KSTAGES; s++) {
        const int buf = s % NSTAGE;
        CP_WAIT1();                 // B(s) arrived (pending: s+1, s+2-empty)
        __syncthreads();            // compute(s-1) done; A(s)/B(s) visible

        if (s + 2 < KSTAGES) issue_B(s + 2);
        CP_COMMIT();                // always commit to keep group count aligned

        float4 ar[8];
        if (s + 1 < KSTAGES) load_A(s + 1, ar);

        const uint32_t ab = sb + buf * STAGE_BYTES;
        const uint32_t al = ab + TILE_BYTES;
        const uint32_t bh = ab + 2 * TILE_BYTES;
        const uint32_t bl = ab + 3 * TILE_BYTES;

        compute_kk(ab, al, bh, bl, 0);
        compute_kk(ab, al, bh, bl, 1);

        if (s + 1 < KSTAGES) store_A(s + 1, ar);   // buf (s+1)%3: free since s-2

        compute_kk(ab, al, bh, bl, 2);
        compute_kk(ab, al, bh, bl, 3);
    }

    // ---- epilogue: fragment -> F (row-major [4096, 512]) ----
    const int r_lo = lane >> 2;
    const int c_lo = (lane & 3) * 2;
#pragma unroll
    for (int mt = 0; mt < 4; mt++) {
        const int row0 = bm * 128 + wm * 64 + mt * 16 + r_lo;
#pragma unroll
        for (int nt = 0; nt < 4; nt++) {
            const int col = bn * 128 + wn * 32 + nt * 8 + c_lo;
            float2 v0 = make_float2(c[mt][nt][0], c[mt][nt][1]);
            float2 v1 = make_float2(c[mt][nt][2], c[mt][nt][3]);
            *(float2*)(F + (size_t)row0 * NCOLS + col)       = v0;
            *(float2*)(F + (size_t)(row0 + 8) * NCOLS + col) = v1;
        }
    }
}

// ---------------------------------------------------------------------------
// Kernel 2: w[t,i,j] = softmax_j F[i*64+j, t]  -> g_w[t*4096 + i*64 + j]
// All 256 threads active: 8 threads per t-column, shfl-reduce within 8 lanes.
// ---------------------------------------------------------------------------
__global__ __launch_bounds__(256, 1)
void softmax_kernel(const float* __restrict__ F) {
    __shared__ float tile[64][33];
    const int tc  = blockIdx.x;      // t-chunk of 32
    const int i   = blockIdx.y;
    const int tid = threadIdx.x;

    const int tt = tid & 31;
    const int j0 = tid >> 5;
#pragma unroll
    for (int r = 0; r < 8; r++) {
        const int j = j0 + r * 8;
        tile[j][tt] = F[(size_t)(i * 64 + j) * NCOLS + tc * 32 + tt];
    }
    __syncthreads();

    {
        const int t8 = tid >> 3;     // 0..31 t index
        const int q  = tid & 7;      // 8 threads per t
        float m = -3.402823466e+38f;
#pragma unroll
        for (int r = 0; r < 8; r++) m = fmaxf(m, tile[q * 8 + r][t8]);
        m = fmaxf(m, __shfl_xor_sync(0xffffffffu, m, 1));
        m = fmaxf(m, __shfl_xor_sync(0xffffffffu, m, 2));
        m = fmaxf(m, __shfl_xor_sync(0xffffffffu, m, 4));
        float e[8], ssum = 0.f;
#pragma unroll
        for (int r = 0; r < 8; r++) {
            e[r] = __expf(tile[q * 8 + r][t8] - m);
            ssum += e[r];
        }
        ssum += __shfl_xor_sync(0xffffffffu, ssum, 1);
        ssum += __shfl_xor_sync(0xffffffffu, ssum, 2);
        ssum += __shfl_xor_sync(0xffffffffu, ssum, 4);
        const float inv = 1.f / ssum;
#pragma unroll
        for (int r = 0; r < 8; r++) tile[q * 8 + r][t8] = e[r] * inv;
    }
    __syncthreads();

#pragma unroll
    for (int idx = 0; idx < 8; idx++) {
        const int lin = tid + idx * 256;
        const int ttw = lin >> 6;
        const int j   = lin & 63;
        g_w[(size_t)(tc * 32 + ttw) * KDIM + i * 64 + j] = tile[j][ttw];
    }
}

// ---------------------------------------------------------------------------
// Kernel 3: Z[b,n] = sum_{p,m} w[x_i[b,p], n, m] * x[b, m, p]
// ---------------------------------------------------------------------------
__global__ __launch_bounds__(256, 1)
void gather_kernel(const float* __restrict__ x,
                   const int* __restrict__ xi,
                   float* __restrict__ Z) {
    __shared__ float xs[NN * PP];
    __shared__ int   ti[PP];
    __shared__ float part[4][NN];

    const int b   = blockIdx.x;
    const int tid = threadIdx.x;

#pragma unroll
    for (int r = 0; r < 8; r++) {
        const int idx = tid + r * 256;
        xs[idx] = x[(size_t)b * (NN * PP) + idx];
    }
    if (tid < PP) ti[tid] = xi[b * PP + tid];
    __syncthreads();

    const int n = tid & 63;
    const int s = tid >> 6;
    float acc = 0.f;
#pragma unroll
    for (int pp = 0; pp < 8; pp++) {
        const int p = s * 8 + pp;
        const int t = ti[p];
        const float4* row = (const float4*)(g_w + (size_t)t * KDIM + n * 64);
#pragma unroll
        for (int q = 0; q < 16; q++) {
            const float4 v = row[q];
            const int m = q * 4;
            acc += v.x * xs[(m + 0) * 32 + p];
            acc += v.y * xs[(m + 1) * 32 + p];
            acc += v.z * xs[(m + 2) * 32 + p];
            acc += v.w * xs[(m + 3) * 32 + p];
        }
    }
    part[s][n] = acc;
    __syncthreads();
    if (tid < NN) {
        Z[b * NN + tid] =
            part[0][tid] + part[1][tid] + part[2][tid] + part[3][tid];
    }
}

// ---------------------------------------------------------------------------
// Launch. Inputs: x [B,N,P] f32, x_i [B,P] i32, g [4096,4096] f32,
//                 weights [4096,512] f32.  Output: Z (4096 f32) then F.
// ---------------------------------------------------------------------------
extern "C" void kernel_launch(void* const* d_in, const int* in_sizes, int n_in,
                              void* d_out, int out_size) {
    const float* x   = (const float*)d_in[0];
    const int*   xi  = (const int*)d_in[1];
    const float* g   = (const float*)d_in[2];
    const float* wts = (const float*)d_in[3];

    float* Z = (float*)d_out;
    float* F = (float*)d_out + NN * NN;

    cudaFuncSetAttribute(mma_gemm_kernel,
                         cudaFuncAttributeMaxDynamicSharedMemorySize, SMEM_TOTAL);

    split_w_kernel<<<dim3(KDIM / 32, NCOLS / 32), 256>>>(wts);

    mma_gemm_kernel<<<dim3(NCOLS / 128, KDIM / 128), 256, SMEM_TOTAL>>>(g, F);

    softmax_kernel<<<dim3(TT / 32, NN), 256>>>(F);
    gather_kernel<<<BB, 256>>>(x, xi, Z);
}

// round 7
// speedup vs baseline: 1.0364x; 1.0364x over previous
#include <cuda_runtime.h>
#include <cuda_bf16.h>
#include <cstdint>

// Problem constants
#define NN      64
#define TT      512
#define BB      64
#define PP      32
#define KDIM    4096        // N*N
#define NCOLS   512         // T

// ---------------------------------------------------------------------------
// Device scratch (static — allocation-free per harness rules)
// ---------------------------------------------------------------------------
__device__ float g_w[TT * KDIM];                       // softmaxed adjacency, 8 MB
__device__ __nv_bfloat16 g_hi[(size_t)KDIM * KDIM];    // 33.5 MB
__device__ __nv_bfloat16 g_lo[(size_t)KDIM * KDIM];    // 33.5 MB
__device__ __nv_bfloat16 w2t_hi[(size_t)NCOLS * KDIM]; // 4 MB
__device__ __nv_bfloat16 w2t_lo[(size_t)NCOLS * KDIM]; // 4 MB
__device__ float g_Fp[(size_t)KDIM * NCOLS];           // split-K partial, 8 MB
__device__ float g_Zp[4][BB * NN];                     // gather partials

// ---------------------------------------------------------------------------
// PTX helpers (baseline PTX, valid on plain sm_103 target)
// ---------------------------------------------------------------------------
__device__ __forceinline__ uint32_t smem_u32(const void* p) {
    uint32_t a;
    asm("{ .reg .u64 t; cvta.to.shared.u64 t, %1; cvt.u32.u64 %0, t; }"
        : "=r"(a) : "l"(p));
    return a;
}

__device__ __forceinline__ void cp16(uint32_t dst, const void* src) {
    asm volatile("cp.async.cg.shared.global [%0], [%1], 16;"
                 :: "r"(dst), "l"(src));
}

#define CP_COMMIT() asm volatile("cp.async.commit_group;" ::: "memory")
#define CP_WAIT1()  asm volatile("cp.async.wait_group 1;"  ::: "memory")

#define LDSM4(r, addr)                                                         \
    asm volatile("ldmatrix.sync.aligned.m8n8.x4.shared.b16 "                   \
                 "{%0,%1,%2,%3}, [%4];"                                        \
                 : "=r"((r)[0]), "=r"((r)[1]), "=r"((r)[2]), "=r"((r)[3])      \
                 : "r"(addr))

#define MMA16816(c, a, b0, b1)                                                 \
    asm volatile("mma.sync.aligned.m16n8k16.row.col.f32.bf16.bf16.f32 "        \
                 "{%0,%1,%2,%3},{%4,%5,%6,%7},{%8,%9},{%0,%1,%2,%3};"          \
                 : "+f"((c)[0]), "+f"((c)[1]), "+f"((c)[2]), "+f"((c)[3])      \
                 : "r"((a)[0]), "r"((a)[1]), "r"((a)[2]), "r"((a)[3]),         \
                   "r"(b0), "r"(b1))

// SW64 swizzle for 64-byte rows: XOR c16 (bits 4:5) with row bits 1:2.
// For ldmatrix over 8/16 consecutive rows this is 128B-slot conflict-free.
__device__ __forceinline__ uint32_t swz64(uint32_t off) {
    return off ^ ((off >> 3) & 0x30);
}

// ---------------------------------------------------------------------------
// Kernel 0a: split g (fp32) into bf16 hi/lo
// ---------------------------------------------------------------------------
__global__ __launch_bounds__(256, 4)
void split_g_kernel(const float* __restrict__ g) {
    const int i = blockIdx.x * 256 + threadIdx.x;
    const float4 v = ((const float4*)g)[i];
    const __nv_bfloat16 h0 = __float2bfloat16(v.x);
    const __nv_bfloat16 h1 = __float2bfloat16(v.y);
    const __nv_bfloat16 h2 = __float2bfloat16(v.z);
    const __nv_bfloat16 h3 = __float2bfloat16(v.w);
    const __nv_bfloat16 l0 = __float2bfloat16(v.x - __bfloat162float(h0));
    const __nv_bfloat16 l1 = __float2bfloat16(v.y - __bfloat162float(h1));
    const __nv_bfloat16 l2 = __float2bfloat16(v.z - __bfloat162float(h2));
    const __nv_bfloat16 l3 = __float2bfloat16(v.w - __bfloat162float(h3));
    uint2 hp, lp;
    hp.x = ((uint32_t)__bfloat16_as_ushort(h1) << 16) | __bfloat16_as_ushort(h0);
    hp.y = ((uint32_t)__bfloat16_as_ushort(h3) << 16) | __bfloat16_as_ushort(h2);
    lp.x = ((uint32_t)__bfloat16_as_ushort(l1) << 16) | __bfloat16_as_ushort(l0);
    lp.y = ((uint32_t)__bfloat16_as_ushort(l3) << 16) | __bfloat16_as_ushort(l2);
    ((uint2*)g_hi)[i] = hp;
    ((uint2*)g_lo)[i] = lp;
}

// ---------------------------------------------------------------------------
// Kernel 0b: weights -> weights^2, transposed to [T=512, K=4096], bf16 hi/lo
// ---------------------------------------------------------------------------
__global__ __launch_bounds__(256, 4)
void split_w_kernel(const float* __restrict__ w) {
    __shared__ float tile[32][33];
    const int kb = blockIdx.x;
    const int nb = blockIdx.y;
    const int tx = threadIdx.x & 31;
    const int ty = threadIdx.x >> 5;
#pragma unroll
    for (int r = 0; r < 4; r++) {
        const int k = kb * 32 + ty + r * 8;
        const float v = w[(size_t)k * NCOLS + nb * 32 + tx];
        tile[ty + r * 8][tx] = v * v;
    }
    __syncthreads();
#pragma unroll
    for (int r = 0; r < 4; r++) {
        const int n = nb * 32 + ty + r * 8;
        const int k = kb * 32 + tx;
        const float val = tile[tx][ty + r * 8];
        const __nv_bfloat16 h = __float2bfloat16(val);
        const __nv_bfloat16 l = __float2bfloat16(val - __bfloat162float(h));
        w2t_hi[(size_t)n * KDIM + k] = h;
        w2t_lo[(size_t)n * KDIM + k] = l;
    }
}

// ---------------------------------------------------------------------------
// Kernel 1: F = g @ weights^2, bf16 hi/lo split HMMA, split-K x2.
//   Grid (4, 32, 2). CTA tile 128x128 over K=2048 per kz half.
//   8 warps (2M x 4N), warp tile 64x32. K-chunk 32 (64B rows, SW64 swizzle).
//   3-stage cp.async pipeline, 32 KB/stage = 96 KB -> 2 CTAs/SM, one wave.
// ---------------------------------------------------------------------------
#define ATILE   8192                       // [128 x 32] bf16
#define STAGE_B (4 * ATILE)                // Ahi|Alo|Bhi|Blo = 32 KB
#define NSTAGE  3
#define SMEM_T  (NSTAGE * STAGE_B)         // 96 KB
#define KHALF   2048
#define KSTAGES (KHALF / 32)               // 64

__global__ __launch_bounds__(256, 2)
void mma_gemm_kernel(float* __restrict__ F) {
    extern __shared__ char smem[];
    const uint32_t sb = smem_u32(smem);
    const int tid  = threadIdx.x;
    const int lane = tid & 31;
    const int wid  = tid >> 5;
    const int bn = blockIdx.x;             // 0..3
    const int bm = blockIdx.y;             // 0..31
    const int kz = blockIdx.z;             // 0..1 (K half)
    const int wm = wid >> 2;               // 0..1
    const int wn = wid & 3;                // 0..3

    const size_t kofs = (size_t)kz * KHALF;
    const __nv_bfloat16* Ah = g_hi   + (size_t)(bm * 128) * KDIM + kofs;
    const __nv_bfloat16* Al = g_lo   + (size_t)(bm * 128) * KDIM + kofs;
    const __nv_bfloat16* Bh = w2t_hi + (size_t)(bn * 128) * KDIM + kofs;
    const __nv_bfloat16* Bl = w2t_lo + (size_t)(bn * 128) * KDIM + kofs;

    float c[4][4][4];
#pragma unroll
    for (int mt = 0; mt < 4; mt++)
#pragma unroll
        for (int nt = 0; nt < 4; nt++)
#pragma unroll
            for (int q = 0; q < 4; q++) c[mt][nt][q] = 0.f;

    // Stage loader: 8 cp16/thread (2 per tile).
    auto issue_stage = [&](int s) {
        const uint32_t base = sb + (s % NSTAGE) * STAGE_B;
        const int ko = s * 32;
#pragma unroll
        for (int j = 0; j < 2; j++) {
            const int id  = tid + j * 256;      // 0..511
            const int row = id >> 2;            // 0..127
            const int c16 = id & 3;
            const uint32_t off = swz64((uint32_t)(row * 64 + c16 * 16));
            const size_t gi = (size_t)row * KDIM + ko + c16 * 8;
            cp16(base + off,             Ah + gi);
            cp16(base + ATILE + off,     Al + gi);
            cp16(base + 2 * ATILE + off, Bh + gi);
            cp16(base + 3 * ATILE + off, Bl + gi);
        }
    };

    issue_stage(0); CP_COMMIT();
    issue_stage(1); CP_COMMIT();

    const int rA    = lane & 15;
    const int kHalf = (lane >> 4) << 4;     // +16B for upper half-warp

    for (int s = 0; s < KSTAGES; s++) {
        CP_WAIT1();
        __syncthreads();
        if (s + 2 < KSTAGES) issue_stage(s + 2);
        CP_COMMIT();

        const uint32_t ab = sb + (s % NSTAGE) * STAGE_B;
        const uint32_t al = ab + ATILE;
        const uint32_t bh = ab + 2 * ATILE;
        const uint32_t bl = ab + 3 * ATILE;

#pragma unroll
        for (int kk = 0; kk < 2; kk++) {    // two K=16 steps per 32-chunk
            const int kb = kk * 32 + kHalf;
            uint32_t ahr[4][4], alr[4][4];
#pragma unroll
            for (int mt = 0; mt < 4; mt++) {
                const int row = wm * 64 + mt * 16 + rA;
                const uint32_t off = swz64((uint32_t)(row * 64 + kb));
                LDSM4(ahr[mt], ab + off);
                LDSM4(alr[mt], al + off);
            }
#pragma unroll
            for (int gg = 0; gg < 2; gg++) {    // keeps B frags short-lived
                uint32_t bhr[4], blr[4];
                const int row = wn * 32 + gg * 16 + rA;
                const uint32_t off = swz64((uint32_t)(row * 64 + kb));
                LDSM4(bhr, bh + off);
                LDSM4(blr, bl + off);
#pragma unroll
                for (int mt = 0; mt < 4; mt++)
#pragma unroll
                    for (int h = 0; h < 2; h++) {
                        const int nt = gg * 2 + h;
                        MMA16816(c[mt][nt], ahr[mt], bhr[h], bhr[h + 2]);
                        MMA16816(c[mt][nt], ahr[mt], blr[h], blr[h + 2]);
                        MMA16816(c[mt][nt], alr[mt], bhr[h], bhr[h + 2]);
                    }
            }
        }
        __syncthreads();
    }

    // Epilogue: kz=0 -> F, kz=1 -> partial buffer
    float* out = kz ? g_Fp : F;
    const int r_lo = lane >> 2;
    const int c_lo = (lane & 3) * 2;
#pragma unroll
    for (int mt = 0; mt < 4; mt++) {
        const int row0 = bm * 128 + wm * 64 + mt * 16 + r_lo;
#pragma unroll
        for (int nt = 0; nt < 4; nt++) {
            const int col = bn * 128 + wn * 32 + nt * 8 + c_lo;
            float2 v0 = make_float2(c[mt][nt][0], c[mt][nt][1]);
            float2 v1 = make_float2(c[mt][nt][2], c[mt][nt][3]);
            *(float2*)(out + (size_t)row0 * NCOLS + col)       = v0;
            *(float2*)(out + (size_t)(row0 + 8) * NCOLS + col) = v1;
        }
    }
}

// ---------------------------------------------------------------------------
// Kernel 1b: F += partial (split-K reduce)
// ---------------------------------------------------------------------------
__global__ __launch_bounds__(256, 4)
void reduce_kernel(float* __restrict__ F) {
    const int i = blockIdx.x * 256 + threadIdx.x;
    float4 a = ((const float4*)F)[i];
    const float4 b = ((const float4*)g_Fp)[i];
    a.x += b.x; a.y += b.y; a.z += b.z; a.w += b.w;
    ((float4*)F)[i] = a;
}

// ---------------------------------------------------------------------------
// Kernel 2: w[t,i,j] = softmax_j F[i*64+j, t]  -> g_w[t*4096 + i*64 + j]
// ---------------------------------------------------------------------------
__global__ __launch_bounds__(256, 1)
void softmax_kernel(const float* __restrict__ F) {
    __shared__ float tile[64][33];
    const int tc  = blockIdx.x;
    const int i   = blockIdx.y;
    const int tid = threadIdx.x;

    const int tt = tid & 31;
    const int j0 = tid >> 5;
#pragma unroll
    for (int r = 0; r < 8; r++) {
        const int j = j0 + r * 8;
        tile[j][tt] = F[(size_t)(i * 64 + j) * NCOLS + tc * 32 + tt];
    }
    __syncthreads();

    {
        const int t8 = tid >> 3;
        const int q  = tid & 7;
        float m = -3.402823466e+38f;
#pragma unroll
        for (int r = 0; r < 8; r++) m = fmaxf(m, tile[q * 8 + r][t8]);
        m = fmaxf(m, __shfl_xor_sync(0xffffffffu, m, 1));
        m = fmaxf(m, __shfl_xor_sync(0xffffffffu, m, 2));
        m = fmaxf(m, __shfl_xor_sync(0xffffffffu, m, 4));
        float e[8], ssum = 0.f;
#pragma unroll
        for (int r = 0; r < 8; r++) {
            e[r] = __expf(tile[q * 8 + r][t8] - m);
            ssum += e[r];
        }
        ssum += __shfl_xor_sync(0xffffffffu, ssum, 1);
        ssum += __shfl_xor_sync(0xffffffffu, ssum, 2);
        ssum += __shfl_xor_sync(0xffffffffu, ssum, 4);
        const float inv = 1.f / ssum;
#pragma unroll
        for (int r = 0; r < 8; r++) tile[q * 8 + r][t8] = e[r] * inv;
    }
    __syncthreads();

#pragma unroll
    for (int idx = 0; idx < 8; idx++) {
        const int lin = tid + idx * 256;
        const int ttw = lin >> 6;
        const int j   = lin & 63;
        g_w[(size_t)(tc * 32 + ttw) * KDIM + i * 64 + j] = tile[j][ttw];
    }
}

// ---------------------------------------------------------------------------
// Kernel 3: gather partials. Grid (B, 4): block z handles p = z*8 .. z*8+7.
// Thread (s = tid/64 in 0..3, n = tid%64) handles 2 p's. Writes g_Zp[z].
// ---------------------------------------------------------------------------
__global__ __launch_bounds__(256, 4)
void gather_kernel(const float* __restrict__ x,
                   const int* __restrict__ xi) {
    __shared__ float xs[NN * PP];
    __shared__ int   ti[8];
    __shared__ float part[4][NN];

    const int b   = blockIdx.x;
    const int z   = blockIdx.y;
    const int tid = threadIdx.x;

#pragma unroll
    for (int r = 0; r < 8; r++) {
        const int idx = tid + r * 256;
        xs[idx] = x[(size_t)b * (NN * PP) + idx];
    }
    if (tid < 8) ti[tid] = xi[b * PP + z * 8 + tid];
    __syncthreads();

    const int n = tid & 63;
    const int s = tid >> 6;     // 0..3
    float acc = 0.f;
#pragma unroll
    for (int pp = 0; pp < 2; pp++) {
        const int pl = s * 2 + pp;          // 0..7 within block
        const int p  = z * 8 + pl;          // global window index
        const int t  = ti[pl];
        const float4* row = (const float4*)(g_w + (size_t)t * KDIM + n * 64);
#pragma unroll
        for (int q = 0; q < 16; q++) {
            const float4 v = row[q];
            const int m = q * 4;
            acc += v.x * xs[(m + 0) * 32 + p];
            acc += v.y * xs[(m + 1) * 32 + p];
            acc += v.z * xs[(m + 2) * 32 + p];
            acc += v.w * xs[(m + 3) * 32 + p];
        }
    }
    part[s][n] = acc;
    __syncthreads();
    if (tid < NN) {
        g_Zp[z][b * NN + tid] =
            part[0][tid] + part[1][tid] + part[2][tid] + part[3][tid];
    }
}

// ---------------------------------------------------------------------------
// Kernel 3b: Z = sum over the 4 gather partials (deterministic, no atomics)
// ---------------------------------------------------------------------------
__global__ __launch_bounds__(256, 4)
void zfinal_kernel(float* __restrict__ Z) {
    const int i = blockIdx.x * 256 + threadIdx.x;   // 0..4095
    Z[i] = g_Zp[0][i] + g_Zp[1][i] + g_Zp[2][i] + g_Zp[3][i];
}

// ---------------------------------------------------------------------------
// Launch. Inputs: x [B,N,P] f32, x_i [B,P] i32, g [4096,4096] f32,
//                 weights [4096,512] f32.  Output: Z (4096 f32) then F.
// ---------------------------------------------------------------------------
extern "C" void kernel_launch(void* const* d_in, const int* in_sizes, int n_in,
                              void* d_out, int out_size) {
    const float* x   = (const float*)d_in[0];
    const int*   xi  = (const int*)d_in[1];
    const float* g   = (const float*)d_in[2];
    const float* wts = (const float*)d_in[3];

    float* Z = (float*)d_out;
    float* F = (float*)d_out + NN * NN;

    cudaFuncSetAttribute(mma_gemm_kernel,
                         cudaFuncAttributeMaxDynamicSharedMemorySize, SMEM_T);

    split_g_kernel<<<(KDIM * (size_t)KDIM) / 4 / 256, 256>>>(g);
    split_w_kernel<<<dim3(KDIM / 32, NCOLS / 32), 256>>>(wts);

    mma_gemm_kernel<<<dim3(NCOLS / 128, KDIM / 128, 2), 256, SMEM_T>>>(F);
    reduce_kernel<<<(KDIM * NCOLS) / 4 / 256, 256>>>(F);

    softmax_kernel<<<dim3(TT / 32, NN), 256>>>(F);

    gather_kernel<<<dim3(BB, 4), 256>>>(x, xi);
    zfinal_kernel<<<(BB * NN) / 256, 256>>>(Z);
}

// round 8
// speedup vs baseline: 1.0966x; 1.0581x over previous
#include <cuda_runtime.h>
#include <cuda_bf16.h>
#include <cstdint>

// Problem constants
#define NN      64
#define TT      512
#define BB      64
#define PP      32
#define KDIM    4096        // N*N
#define NCOLS   512         // T

// ---------------------------------------------------------------------------
// Device scratch (static — allocation-free per harness rules)
// Split operands are stored TILED: tile = [128 rows x 32 k] bf16 = 8 KB
// contiguous, SW64-swizzled, so the GEMM can fetch a stage with 4 bulk copies.
//   A tiles: tile_id = bm*128 + kc   (bm 0..31, kc 0..127)
//   B tiles: tile_id = bn*128 + kc   (bn 0..3,  kc 0..127)
// ---------------------------------------------------------------------------
__device__ float g_w[TT * KDIM];                         // softmaxed adjacency
__device__ __nv_bfloat16 g_hi_t[(size_t)KDIM * KDIM];    // 33.5 MB tiled
__device__ __nv_bfloat16 g_lo_t[(size_t)KDIM * KDIM];    // 33.5 MB tiled
__device__ __nv_bfloat16 w2t_hi_t[(size_t)NCOLS * KDIM]; // 4 MB tiled
__device__ __nv_bfloat16 w2t_lo_t[(size_t)NCOLS * KDIM]; // 4 MB tiled
__device__ float g_Zp[4][BB * NN];                       // gather partials

// ---------------------------------------------------------------------------
// PTX helpers (baseline sm_90-level PTX, valid on plain sm_103 target)
// ---------------------------------------------------------------------------
__device__ __forceinline__ uint32_t smem_u32(const void* p) {
    uint32_t a;
    asm("{ .reg .u64 t; cvta.to.shared.u64 t, %1; cvt.u32.u64 %0, t; }"
        : "=r"(a) : "l"(p));
    return a;
}

__device__ __forceinline__ void cp_bulk8k(uint32_t dst, const void* src,
                                          uint32_t mbar) {
    asm volatile(
        "cp.async.bulk.shared::cluster.global.mbarrier::complete_tx::bytes "
        "[%0], [%1], %2, [%3];"
        :: "r"(dst), "l"(src), "r"(8192u), "r"(mbar) : "memory");
}

__device__ __forceinline__ void mbar_init(uint32_t mbar, uint32_t cnt) {
    asm volatile("mbarrier.init.shared.b64 [%0], %1;" :: "r"(mbar), "r"(cnt)
                 : "memory");
}

__device__ __forceinline__ void mbar_expect_tx(uint32_t mbar, uint32_t bytes) {
    asm volatile("mbarrier.arrive.expect_tx.shared.b64 _, [%0], %1;"
                 :: "r"(mbar), "r"(bytes) : "memory");
}

__device__ __forceinline__ void mbar_wait(uint32_t mbar, uint32_t parity) {
    asm volatile(
        "{\n\t"
        ".reg .pred P1;\n\t"
        "WAIT_LOOP_%=:\n\t"
        "mbarrier.try_wait.parity.acquire.cta.shared::cta.b64 P1, [%0], %1, 0x989680;\n\t"
        "@P1 bra.uni WAIT_DONE_%=;\n\t"
        "bra.uni WAIT_LOOP_%=;\n\t"
        "WAIT_DONE_%=:\n\t"
        "}"
        :: "r"(mbar), "r"(parity) : "memory");
}

#define LDSM4(r, addr)                                                         \
    asm volatile("ldmatrix.sync.aligned.m8n8.x4.shared.b16 "                   \
                 "{%0,%1,%2,%3}, [%4];"                                        \
                 : "=r"((r)[0]), "=r"((r)[1]), "=r"((r)[2]), "=r"((r)[3])      \
                 : "r"(addr))

#define MMA16816(c, a, b0, b1)                                                 \
    asm volatile("mma.sync.aligned.m16n8k16.row.col.f32.bf16.bf16.f32 "        \
                 "{%0,%1,%2,%3},{%4,%5,%6,%7},{%8,%9},{%0,%1,%2,%3};"          \
                 : "+f"((c)[0]), "+f"((c)[1]), "+f"((c)[2]), "+f"((c)[3])      \
                 : "r"((a)[0]), "r"((a)[1]), "r"((a)[2]), "r"((a)[3]),         \
                   "r"(b0), "r"(b1))

// SW64 swizzle for 64-byte rows (conflict-free ldmatrix, proven R7)
__device__ __forceinline__ uint32_t swz64(uint32_t off) {
    return off ^ ((off >> 3) & 0x30);
}

__device__ __forceinline__ uint32_t pk_hi(float x, float y) {
    return ((uint32_t)__bfloat16_as_ushort(__float2bfloat16(y)) << 16) |
           __bfloat16_as_ushort(__float2bfloat16(x));
}
__device__ __forceinline__ uint32_t pk_lo(float x, float y) {
    const float lx = x - __bfloat162float(__float2bfloat16(x));
    const float ly = y - __bfloat162float(__float2bfloat16(y));
    return pk_hi(lx, ly);
}
__device__ __forceinline__ void pack8(const float4& u, const float4& v,
                                      uint4& h, uint4& l) {
    h.x = pk_hi(u.x, u.y); h.y = pk_hi(u.z, u.w);
    h.z = pk_hi(v.x, v.y); h.w = pk_hi(v.z, v.w);
    l.x = pk_lo(u.x, u.y); l.y = pk_lo(u.z, u.w);
    l.z = pk_lo(v.x, v.y); l.w = pk_lo(v.z, v.w);
}

// ---------------------------------------------------------------------------
// Kernel 0a: split g (fp32, row-major) into bf16 hi/lo TILED+SWIZZLED layout
// ---------------------------------------------------------------------------
__global__ __launch_bounds__(256, 4)
void split_g_kernel(const float* __restrict__ g) {
    const int idx = blockIdx.x * 256 + threadIdx.x;   // one per 8 floats
    const int row = idx >> 9;                         // 0..4095
    const int c8  = idx & 511;                        // 8-float group in row
    const float* p = g + (size_t)row * KDIM + c8 * 8;
    const float4 v0 = *(const float4*)p;
    const float4 v1 = *(const float4*)(p + 4);
    uint4 h, l;
    pack8(v0, v1, h, l);
    const int bm = row >> 7, r = row & 127;
    const int kc = c8 >> 2, c16 = c8 & 3;
    const size_t tbase = (size_t)(bm * 128 + kc) * 8192;
    const uint32_t off = swz64((uint32_t)(r * 64 + c16 * 16));
    *(uint4*)((char*)g_hi_t + tbase + off) = h;
    *(uint4*)((char*)g_lo_t + tbase + off) = l;
}

// ---------------------------------------------------------------------------
// Kernel 0b: weights [K=4096, T=512] -> (w^2)^T tiled bf16 hi/lo.
// Grid (kc=128, bn=4); block produces one output tile (bn, kc).
// ---------------------------------------------------------------------------
__global__ __launch_bounds__(256, 2)
void split_w_kernel(const float* __restrict__ w) {
    __shared__ float tile[128][33];   // [t_local][k_local]
    const int kc = blockIdx.x;        // K chunk of 32
    const int bn = blockIdx.y;        // T block of 128
    const int tid = threadIdx.x;

#pragma unroll
    for (int j = 0; j < 16; j++) {
        const int id = tid + j * 256;        // 0..4095
        const int kl = id >> 7;              // 0..31
        const int tl = id & 127;             // 0..127
        const float v = w[(size_t)(kc * 32 + kl) * NCOLS + bn * 128 + tl];
        tile[tl][kl] = v * v;
    }
    __syncthreads();

    const size_t tbase = (size_t)(bn * 128 + kc) * 8192;
#pragma unroll
    for (int j = 0; j < 2; j++) {
        const int id = tid + j * 256;        // 0..511
        const int r  = id >> 2;              // t row 0..127
        const int c16 = id & 3;
        float4 u, v;
        u.x = tile[r][c16 * 8 + 0]; u.y = tile[r][c16 * 8 + 1];
        u.z = tile[r][c16 * 8 + 2]; u.w = tile[r][c16 * 8 + 3];
        v.x = tile[r][c16 * 8 + 4]; v.y = tile[r][c16 * 8 + 5];
        v.z = tile[r][c16 * 8 + 6]; v.w = tile[r][c16 * 8 + 7];
        uint4 h, l;
        pack8(u, v, h, l);
        const uint32_t off = swz64((uint32_t)(r * 64 + c16 * 16));
        *(uint4*)((char*)w2t_hi_t + tbase + off) = h;
        *(uint4*)((char*)w2t_lo_t + tbase + off) = l;
    }
}

// ---------------------------------------------------------------------------
// Kernel 1: F = g @ weights^2, bf16 hi/lo split HMMA, TMA-bulk loads.
//   Grid (4, 32). CTA tile 128x128 over K=4096. 8 warps (2M x 4N),
//   warp tile 64x32. 128 stages of K=32; stage = 4 x 8KB bulk copies.
//   4-slot mbarrier ring, 128 KB smem, 1 CTA/SM (grid 128 = one wave).
// ---------------------------------------------------------------------------
#define ATILE   8192
#define STAGE_B (4 * ATILE)                // 32 KB
#define NSLOT   4
#define SMEM_T  (NSLOT * STAGE_B)          // 128 KB
#define KSTAGES (KDIM / 32)                // 128

__global__ __launch_bounds__(256, 1)
void mma_gemm_kernel(float* __restrict__ F) {
    extern __shared__ char smem[];
    __shared__ uint64_t mbars[NSLOT];
    const uint32_t sb = smem_u32(smem);
    const uint32_t mb0 = smem_u32(&mbars[0]);
    const int tid  = threadIdx.x;
    const int lane = tid & 31;
    const int wid  = tid >> 5;
    const int bn = blockIdx.x;             // 0..3
    const int bm = blockIdx.y;             // 0..31
    const int wm = wid >> 2;               // 0..1
    const int wn = wid & 3;                // 0..3

    const char* Ah = (const char*)g_hi_t   + (size_t)(bm * 128) * 8192;
    const char* Al = (const char*)g_lo_t   + (size_t)(bm * 128) * 8192;
    const char* Bh = (const char*)w2t_hi_t + (size_t)(bn * 128) * 8192;
    const char* Bl = (const char*)w2t_lo_t + (size_t)(bn * 128) * 8192;

    if (tid == 0) {
#pragma unroll
        for (int i = 0; i < NSLOT; i++) mbar_init(mb0 + i * 8, 1);
    }
    __syncthreads();

    auto issue = [&](int s) {
        const int slot = s & (NSLOT - 1);
        const uint32_t mb  = mb0 + slot * 8;
        const uint32_t dst = sb + slot * STAGE_B;
        mbar_expect_tx(mb, STAGE_B);
        const size_t to = (size_t)s * 8192;
        cp_bulk8k(dst,             Ah + to, mb);
        cp_bulk8k(dst + ATILE,     Al + to, mb);
        cp_bulk8k(dst + 2 * ATILE, Bh + to, mb);
        cp_bulk8k(dst + 3 * ATILE, Bl + to, mb);
    };

    if (tid == 0) { issue(0); issue(1); issue(2); }

    float c[4][4][4];
#pragma unroll
    for (int mt = 0; mt < 4; mt++)
#pragma unroll
        for (int nt = 0; nt < 4; nt++)
#pragma unroll
            for (int q = 0; q < 4; q++) c[mt][nt][q] = 0.f;

    const int rA    = lane & 15;
    const int kHalf = (lane >> 4) << 4;

    for (int s = 0; s < KSTAGES; s++) {
        const int slot = s & (NSLOT - 1);
        // Issue 3 stages ahead: slot (s+3)%4 was used by stage s-1 whose
        // compute finished before last iteration's __syncthreads.
        if (tid == 0 && s + 3 < KSTAGES) issue(s + 3);

        mbar_wait(mb0 + slot * 8, (s >> 2) & 1);

        const uint32_t ab = sb + slot * STAGE_B;
        const uint32_t al = ab + ATILE;
        const uint32_t bh = ab + 2 * ATILE;
        const uint32_t bl = ab + 3 * ATILE;

#pragma unroll
        for (int kk = 0; kk < 2; kk++) {
            const int kb = kk * 32 + kHalf;
            uint32_t ahr[4][4], alr[4][4];
#pragma unroll
            for (int mt = 0; mt < 4; mt++) {
                const int row = wm * 64 + mt * 16 + rA;
                const uint32_t off = swz64((uint32_t)(row * 64 + kb));
                LDSM4(ahr[mt], ab + off);
                LDSM4(alr[mt], al + off);
            }
#pragma unroll
            for (int gg = 0; gg < 2; gg++) {
                uint32_t bhr[4], blr[4];
                const int row = wn * 32 + gg * 16 + rA;
                const uint32_t off = swz64((uint32_t)(row * 64 + kb));
                LDSM4(bhr, bh + off);
                LDSM4(blr, bl + off);
                // hh pass, then hl, then lh: same-accumulator distance = 8
#pragma unroll
                for (int mt = 0; mt < 4; mt++)
#pragma unroll
                    for (int h = 0; h < 2; h++)
                        MMA16816(c[mt][gg * 2 + h], ahr[mt], bhr[h], bhr[h + 2]);
#pragma unroll
                for (int mt = 0; mt < 4; mt++)
#pragma unroll
                    for (int h = 0; h < 2; h++)
                        MMA16816(c[mt][gg * 2 + h], ahr[mt], blr[h], blr[h + 2]);
#pragma unroll
                for (int mt = 0; mt < 4; mt++)
#pragma unroll
                    for (int h = 0; h < 2; h++)
                        MMA16816(c[mt][gg * 2 + h], alr[mt], bhr[h], bhr[h + 2]);
            }
        }
        __syncthreads();     // all warps done reading slot before reuse
    }

    // Epilogue: fragments -> F (row-major [4096, 512])
    const int r_lo = lane >> 2;
    const int c_lo = (lane & 3) * 2;
#pragma unroll
    for (int mt = 0; mt < 4; mt++) {
        const int row0 = bm * 128 + wm * 64 + mt * 16 + r_lo;
#pragma unroll
        for (int nt = 0; nt < 4; nt++) {
            const int col = bn * 128 + wn * 32 + nt * 8 + c_lo;
            float2 v0 = make_float2(c[mt][nt][0], c[mt][nt][1]);
            float2 v1 = make_float2(c[mt][nt][2], c[mt][nt][3]);
            *(float2*)(F + (size_t)row0 * NCOLS + col)       = v0;
            *(float2*)(F + (size_t)(row0 + 8) * NCOLS + col) = v1;
        }
    }
}

// ---------------------------------------------------------------------------
// Kernel 2: w[t,i,j] = softmax_j F[i*64+j, t]  -> g_w[t*4096 + i*64 + j]
// ---------------------------------------------------------------------------
__global__ __launch_bounds__(256, 1)
void softmax_kernel(const float* __restrict__ F) {
    __shared__ float tile[64][33];
    const int tc  = blockIdx.x;
    const int i   = blockIdx.y;
    const int tid = threadIdx.x;

    const int tt = tid & 31;
    const int j0 = tid >> 5;
#pragma unroll
    for (int r = 0; r < 8; r++) {
        const int j = j0 + r * 8;
        tile[j][tt] = F[(size_t)(i * 64 + j) * NCOLS + tc * 32 + tt];
    }
    __syncthreads();

    {
        const int t8 = tid >> 3;
        const int q  = tid & 7;
        float m = -3.402823466e+38f;
#pragma unroll
        for (int r = 0; r < 8; r++) m = fmaxf(m, tile[q * 8 + r][t8]);
        m = fmaxf(m, __shfl_xor_sync(0xffffffffu, m, 1));
        m = fmaxf(m, __shfl_xor_sync(0xffffffffu, m, 2));
        m = fmaxf(m, __shfl_xor_sync(0xffffffffu, m, 4));
        float e[8], ssum = 0.f;
#pragma unroll
        for (int r = 0; r < 8; r++) {
            e[r] = __expf(tile[q * 8 + r][t8] - m);
            ssum += e[r];
        }
        ssum += __shfl_xor_sync(0xffffffffu, ssum, 1);
        ssum += __shfl_xor_sync(0xffffffffu, ssum, 2);
        ssum += __shfl_xor_sync(0xffffffffu, ssum, 4);
        const float inv = 1.f / ssum;
#pragma unroll
        for (int r = 0; r < 8; r++) tile[q * 8 + r][t8] = e[r] * inv;
    }
    __syncthreads();

#pragma unroll
    for (int idx = 0; idx < 8; idx++) {
        const int lin = tid + idx * 256;
        const int ttw = lin >> 6;
        const int j   = lin & 63;
        g_w[(size_t)(tc * 32 + ttw) * KDIM + i * 64 + j] = tile[j][ttw];
    }
}

// ---------------------------------------------------------------------------
// Kernel 3: gather partials. Grid (B, 4): block z handles p = z*8 .. z*8+7.
// ---------------------------------------------------------------------------
__global__ __launch_bounds__(256, 4)
void gather_kernel(const float* __restrict__ x,
                   const int* __restrict__ xi) {
    __shared__ float xs[NN * PP];
    __shared__ int   ti[8];
    __shared__ float part[4][NN];

    const int b   = blockIdx.x;
    const int z   = blockIdx.y;
    const int tid = threadIdx.x;

#pragma unroll
    for (int r = 0; r < 8; r++) {
        const int idx = tid + r * 256;
        xs[idx] = x[(size_t)b * (NN * PP) + idx];
    }
    if (tid < 8) ti[tid] = xi[b * PP + z * 8 + tid];
    __syncthreads();

    const int n = tid & 63;
    const int s = tid >> 6;
    float acc = 0.f;
#pragma unroll
    for (int pp = 0; pp < 2; pp++) {
        const int pl = s * 2 + pp;
        const int p  = z * 8 + pl;
        const int t  = ti[pl];
        const float4* row = (const float4*)(g_w + (size_t)t * KDIM + n * 64);
#pragma unroll
        for (int q = 0; q < 16; q++) {
            const float4 v = row[q];
            const int m = q * 4;
            acc += v.x * xs[(m + 0) * 32 + p];
            acc += v.y * xs[(m + 1) * 32 + p];
            acc += v.z * xs[(m + 2) * 32 + p];
            acc += v.w * xs[(m + 3) * 32 + p];
        }
    }
    part[s][n] = acc;
    __syncthreads();
    if (tid < NN) {
        g_Zp[z][b * NN + tid] =
            part[0][tid] + part[1][tid] + part[2][tid] + part[3][tid];
    }
}

__global__ __launch_bounds__(256, 4)
void zfinal_kernel(float* __restrict__ Z) {
    const int i = blockIdx.x * 256 + threadIdx.x;
    Z[i] = g_Zp[0][i] + g_Zp[1][i] + g_Zp[2][i] + g_Zp[3][i];
}

// ---------------------------------------------------------------------------
// Launch. Inputs: x [B,N,P] f32, x_i [B,P] i32, g [4096,4096] f32,
//                 weights [4096,512] f32.  Output: Z (4096 f32) then F.
// ---------------------------------------------------------------------------
extern "C" void kernel_launch(void* const* d_in, const int* in_sizes, int n_in,
                              void* d_out, int out_size) {
    const float* x   = (const float*)d_in[0];
    const int*   xi  = (const int*)d_in[1];
    const float* g   = (const float*)d_in[2];
    const float* wts = (const float*)d_in[3];

    float* Z = (float*)d_out;
    float* F = (float*)d_out + NN * NN;

    cudaFuncSetAttribute(mma_gemm_kernel,
                         cudaFuncAttributeMaxDynamicSharedMemorySize, SMEM_T);

    split_g_kernel<<<(KDIM * (size_t)KDIM) / 8 / 256, 256>>>(g);
    split_w_kernel<<<dim3(KDIM / 32, NCOLS / 128), 256>>>(wts);

    mma_gemm_kernel<<<dim3(NCOLS / 128, KDIM / 128), 256, SMEM_T>>>(F);

    softmax_kernel<<<dim3(TT / 32, NN), 256>>>(F);

    gather_kernel<<<dim3(BB, 4), 256>>>(x, xi);
    zfinal_kernel<<<(BB * NN) / 256, 256>>>(Z);
}

// round 9
// speedup vs baseline: 1.1188x; 1.0202x over previous
#include <cuda_runtime.h>
#include <cuda_bf16.h>
#include <cstdint>

// Problem constants
#define NN      64
#define TT      512
#define BB      64
#define PP      32
#define KDIM    4096        // N*N
#define NCOLS   512         // T

// ---------------------------------------------------------------------------
// Device scratch (static — allocation-free per harness rules)
// Split operands stored TILED: tile = [128 rows x 32 k] bf16 = 8 KB
// contiguous, SW64-swizzled; GEMM fetches a stage with 4 TMA bulk copies.
//   A tiles: tile_id = bm*128 + kc   (bm 0..31, kc 0..127)
//   B tiles: tile_id = bn*128 + kc   (bn 0..3,  kc 0..127)
// ---------------------------------------------------------------------------
__device__ float g_w[TT * KDIM];                         // softmaxed adjacency
__device__ __nv_bfloat16 g_hi_t[(size_t)KDIM * KDIM];
__device__ __nv_bfloat16 g_lo_t[(size_t)KDIM * KDIM];
__device__ __nv_bfloat16 w2t_hi_t[(size_t)NCOLS * KDIM];
__device__ __nv_bfloat16 w2t_lo_t[(size_t)NCOLS * KDIM];
__device__ float g_Zp[4][BB * NN];                       // gather partials

// ---------------------------------------------------------------------------
// PTX helpers (baseline sm_90-level PTX, valid on plain sm_103 target)
// ---------------------------------------------------------------------------
__device__ __forceinline__ uint32_t smem_u32(const void* p) {
    uint32_t a;
    asm("{ .reg .u64 t; cvta.to.shared.u64 t, %1; cvt.u32.u64 %0, t; }"
        : "=r"(a) : "l"(p));
    return a;
}

__device__ __forceinline__ void cp_bulk8k(uint32_t dst, const void* src,
                                          uint32_t mbar) {
    asm volatile(
        "cp.async.bulk.shared::cluster.global.mbarrier::complete_tx::bytes "
        "[%0], [%1], %2, [%3];"
        :: "r"(dst), "l"(src), "r"(8192u), "r"(mbar) : "memory");
}

__device__ __forceinline__ void mbar_init(uint32_t mbar, uint32_t cnt) {
    asm volatile("mbarrier.init.shared.b64 [%0], %1;" :: "r"(mbar), "r"(cnt)
                 : "memory");
}

__device__ __forceinline__ void mbar_expect_tx(uint32_t mbar, uint32_t bytes) {
    asm volatile("mbarrier.arrive.expect_tx.shared.b64 _, [%0], %1;"
                 :: "r"(mbar), "r"(bytes) : "memory");
}

__device__ __forceinline__ void mbar_wait(uint32_t mbar, uint32_t parity) {
    asm volatile(
        "{\n\t"
        ".reg .pred P1;\n\t"
        "WAIT_LOOP_%=:\n\t"
        "mbarrier.try_wait.parity.acquire.cta.shared::cta.b64 P1, [%0], %1, 0x989680;\n\t"
        "@P1 bra.uni WAIT_DONE_%=;\n\t"
        "bra.uni WAIT_LOOP_%=;\n\t"
        "WAIT_DONE_%=:\n\t"
        "}"
        :: "r"(mbar), "r"(parity) : "memory");
}

#define LDSM4(r, addr)                                                         \
    asm volatile("ldmatrix.sync.aligned.m8n8.x4.shared.b16 "                   \
                 "{%0,%1,%2,%3}, [%4];"                                        \
                 : "=r"((r)[0]), "=r"((r)[1]), "=r"((r)[2]), "=r"((r)[3])      \
                 : "r"(addr))

#define MMA16816(c, a, b0, b1)                                                 \
    asm volatile("mma.sync.aligned.m16n8k16.row.col.f32.bf16.bf16.f32 "        \
                 "{%0,%1,%2,%3},{%4,%5,%6,%7},{%8,%9},{%0,%1,%2,%3};"          \
                 : "+f"((c)[0]), "+f"((c)[1]), "+f"((c)[2]), "+f"((c)[3])      \
                 : "r"((a)[0]), "r"((a)[1]), "r"((a)[2]), "r"((a)[3]),         \
                   "r"(b0), "r"(b1))

// SW64 swizzle for 64-byte rows (conflict-free ldmatrix, proven)
__device__ __forceinline__ uint32_t swz64(uint32_t off) {
    return off ^ ((off >> 3) & 0x30);
}

__device__ __forceinline__ uint32_t pk_hi(float x, float y) {
    return ((uint32_t)__bfloat16_as_ushort(__float2bfloat16(y)) << 16) |
           __bfloat16_as_ushort(__float2bfloat16(x));
}
__device__ __forceinline__ uint32_t pk_lo(float x, float y) {
    const float lx = x - __bfloat162float(__float2bfloat16(x));
    const float ly = y - __bfloat162float(__float2bfloat16(y));
    return pk_hi(lx, ly);
}
__device__ __forceinline__ void pack8(const float4& u, const float4& v,
                                      uint4& h, uint4& l) {
    h.x = pk_hi(u.x, u.y); h.y = pk_hi(u.z, u.w);
    h.z = pk_hi(v.x, v.y); h.w = pk_hi(v.z, v.w);
    l.x = pk_lo(u.x, u.y); l.y = pk_lo(u.z, u.w);
    l.z = pk_lo(v.x, v.y); l.w = pk_lo(v.z, v.w);
}

// ---------------------------------------------------------------------------
// Kernel 0a: split g (fp32, row-major) into bf16 hi/lo tiled+swizzled.
// Grid (kc=128, bm=32); one block writes one 8KB tile pair, fully coalesced:
// warp covers 8 rows x 128B contiguous in both gmem read and tile write.
// ---------------------------------------------------------------------------
__global__ __launch_bounds__(256, 4)
void split_g_kernel(const float* __restrict__ g) {
    const int kc = blockIdx.x;
    const int bm = blockIdx.y;
    const int tid = threadIdx.x;
    const size_t tbase = (size_t)(bm * 128 + kc) * 8192;
#pragma unroll
    for (int j = 0; j < 2; j++) {
        const int id  = tid + j * 256;      // 0..511
        const int row = id >> 2;            // 0..127
        const int c16 = id & 3;
        const float* p = g + (size_t)(bm * 128 + row) * KDIM + kc * 32 + c16 * 8;
        const float4 v0 = *(const float4*)p;
        const float4 v1 = *(const float4*)(p + 4);
        uint4 h, l;
        pack8(v0, v1, h, l);
        const uint32_t off = swz64((uint32_t)(row * 64 + c16 * 16));
        *(uint4*)((char*)g_hi_t + tbase + off) = h;
        *(uint4*)((char*)g_lo_t + tbase + off) = l;
    }
}

// ---------------------------------------------------------------------------
// Kernel 0b: weights [K=4096, T=512] -> (w^2)^T tiled bf16 hi/lo.
// ---------------------------------------------------------------------------
__global__ __launch_bounds__(256, 2)
void split_w_kernel(const float* __restrict__ w) {
    __shared__ float tile[128][33];   // [t_local][k_local]
    const int kc = blockIdx.x;
    const int bn = blockIdx.y;
    const int tid = threadIdx.x;

#pragma unroll
    for (int j = 0; j < 16; j++) {
        const int id = tid + j * 256;
        const int kl = id >> 7;
        const int tl = id & 127;
        const float v = w[(size_t)(kc * 32 + kl) * NCOLS + bn * 128 + tl];
        tile[tl][kl] = v * v;
    }
    __syncthreads();

    const size_t tbase = (size_t)(bn * 128 + kc) * 8192;
#pragma unroll
    for (int j = 0; j < 2; j++) {
        const int id = tid + j * 256;
        const int r  = id >> 2;
        const int c16 = id & 3;
        float4 u, v;
        u.x = tile[r][c16 * 8 + 0]; u.y = tile[r][c16 * 8 + 1];
        u.z = tile[r][c16 * 8 + 2]; u.w = tile[r][c16 * 8 + 3];
        v.x = tile[r][c16 * 8 + 4]; v.y = tile[r][c16 * 8 + 5];
        v.z = tile[r][c16 * 8 + 6]; v.w = tile[r][c16 * 8 + 7];
        uint4 h, l;
        pack8(u, v, h, l);
        const uint32_t off = swz64((uint32_t)(r * 64 + c16 * 16));
        *(uint4*)((char*)w2t_hi_t + tbase + off) = h;
        *(uint4*)((char*)w2t_lo_t + tbase + off) = l;
    }
}

// ---------------------------------------------------------------------------
// Kernel 1: F = g @ weights^2 (bf16 hi/lo split HMMA, TMA loads) with the
// row-softmax FUSED into the epilogue.
//   Grid (4, 32). CTA tile 128x128 over K=4096. 8 warps (2M x 4N),
//   warp tile 64x32. Warp wm owns the complete i-group (2*bm + wm): the
//   64-row softmax per column is a pure intra-warp shfl reduction.
// ---------------------------------------------------------------------------
#define ATILE   8192
#define STAGE_B (4 * ATILE)                // 32 KB
#define NSLOT   4
#define SMEM_T  (NSLOT * STAGE_B)          // 128 KB
#define KSTAGES (KDIM / 32)                // 128

__global__ __launch_bounds__(256, 1)
void mma_gemm_kernel(float* __restrict__ F) {
    extern __shared__ char smem[];
    __shared__ uint64_t mbars[NSLOT];
    const uint32_t sb = smem_u32(smem);
    const uint32_t mb0 = smem_u32(&mbars[0]);
    const int tid  = threadIdx.x;
    const int lane = tid & 31;
    const int wid  = tid >> 5;
    const int bn = blockIdx.x;             // 0..3
    const int bm = blockIdx.y;             // 0..31
    const int wm = wid >> 2;               // 0..1
    const int wn = wid & 3;                // 0..3

    const char* Ah = (const char*)g_hi_t   + (size_t)(bm * 128) * 8192;
    const char* Al = (const char*)g_lo_t   + (size_t)(bm * 128) * 8192;
    const char* Bh = (const char*)w2t_hi_t + (size_t)(bn * 128) * 8192;
    const char* Bl = (const char*)w2t_lo_t + (size_t)(bn * 128) * 8192;

    if (tid == 0) {
#pragma unroll
        for (int i = 0; i < NSLOT; i++) mbar_init(mb0 + i * 8, 1);
    }
    __syncthreads();

    auto issue = [&](int s) {
        const int slot = s & (NSLOT - 1);
        const uint32_t mb  = mb0 + slot * 8;
        const uint32_t dst = sb + slot * STAGE_B;
        mbar_expect_tx(mb, STAGE_B);
        const size_t to = (size_t)s * 8192;
        cp_bulk8k(dst,             Ah + to, mb);
        cp_bulk8k(dst + ATILE,     Al + to, mb);
        cp_bulk8k(dst + 2 * ATILE, Bh + to, mb);
        cp_bulk8k(dst + 3 * ATILE, Bl + to, mb);
    };

    if (tid == 0) { issue(0); issue(1); issue(2); }

    float c[4][4][4];
#pragma unroll
    for (int mt = 0; mt < 4; mt++)
#pragma unroll
        for (int nt = 0; nt < 4; nt++)
#pragma unroll
            for (int q = 0; q < 4; q++) c[mt][nt][q] = 0.f;

    const int rA    = lane & 15;
    const int kHalf = (lane >> 4) << 4;

    for (int s = 0; s < KSTAGES; s++) {
        const int slot = s & (NSLOT - 1);
        if (tid == 0 && s + 3 < KSTAGES) issue(s + 3);

        mbar_wait(mb0 + slot * 8, (s >> 2) & 1);

        const uint32_t ab = sb + slot * STAGE_B;
        const uint32_t al = ab + ATILE;
        const uint32_t bh = ab + 2 * ATILE;
        const uint32_t bl = ab + 3 * ATILE;

#pragma unroll
        for (int kk = 0; kk < 2; kk++) {
            const int kb = kk * 32 + kHalf;
            uint32_t ahr[4][4], alr[4][4];
#pragma unroll
            for (int mt = 0; mt < 4; mt++) {
                const int row = wm * 64 + mt * 16 + rA;
                const uint32_t off = swz64((uint32_t)(row * 64 + kb));
                LDSM4(ahr[mt], ab + off);
                LDSM4(alr[mt], al + off);
            }
#pragma unroll
            for (int gg = 0; gg < 2; gg++) {
                uint32_t bhr[4], blr[4];
                const int row = wn * 32 + gg * 16 + rA;
                const uint32_t off = swz64((uint32_t)(row * 64 + kb));
                LDSM4(bhr, bh + off);
                LDSM4(blr, bl + off);
#pragma unroll
                for (int mt = 0; mt < 4; mt++)
#pragma unroll
                    for (int h = 0; h < 2; h++)
                        MMA16816(c[mt][gg * 2 + h], ahr[mt], bhr[h], bhr[h + 2]);
#pragma unroll
                for (int mt = 0; mt < 4; mt++)
#pragma unroll
                    for (int h = 0; h < 2; h++)
                        MMA16816(c[mt][gg * 2 + h], ahr[mt], blr[h], blr[h + 2]);
#pragma unroll
                for (int mt = 0; mt < 4; mt++)
#pragma unroll
                    for (int h = 0; h < 2; h++)
                        MMA16816(c[mt][gg * 2 + h], alr[mt], bhr[h], bhr[h + 2]);
            }
        }
        __syncthreads();
    }

    // ---- epilogue 1: write raw F (row-major [4096, 512]) ----
    const int r_lo = lane >> 2;
    const int c_lo = (lane & 3) * 2;
#pragma unroll
    for (int mt = 0; mt < 4; mt++) {
        const int row0 = bm * 128 + wm * 64 + mt * 16 + r_lo;
#pragma unroll
        for (int nt = 0; nt < 4; nt++) {
            const int col = bn * 128 + wn * 32 + nt * 8 + c_lo;
            float2 v0 = make_float2(c[mt][nt][0], c[mt][nt][1]);
            float2 v1 = make_float2(c[mt][nt][2], c[mt][nt][3]);
            *(float2*)(F + (size_t)row0 * NCOLS + col)       = v0;
            *(float2*)(F + (size_t)(row0 + 8) * NCOLS + col) = v1;
        }
    }

    // ---- epilogue 2: fused softmax over the warp's 64 rows, per column ----
    // Column A of pair = fragment slots 0,2; column B = slots 1,3.
    // Lanes with equal (lane&3) hold the same pair of columns; shfl_xor over
    // strides 4/8/16 reduces across r_lo while preserving lane&3.
    float mA[4], mB[4], sA[4], sB[4];
#pragma unroll
    for (int nt = 0; nt < 4; nt++) {
        float ma = -3.402823466e+38f, mb = ma;
#pragma unroll
        for (int mt = 0; mt < 4; mt++) {
            ma = fmaxf(ma, fmaxf(c[mt][nt][0], c[mt][nt][2]));
            mb = fmaxf(mb, fmaxf(c[mt][nt][1], c[mt][nt][3]));
        }
        ma = fmaxf(ma, __shfl_xor_sync(0xffffffffu, ma, 4));
        ma = fmaxf(ma, __shfl_xor_sync(0xffffffffu, ma, 8));
        ma = fmaxf(ma, __shfl_xor_sync(0xffffffffu, ma, 16));
        mb = fmaxf(mb, __shfl_xor_sync(0xffffffffu, mb, 4));
        mb = fmaxf(mb, __shfl_xor_sync(0xffffffffu, mb, 8));
        mb = fmaxf(mb, __shfl_xor_sync(0xffffffffu, mb, 16));
        mA[nt] = ma; mB[nt] = mb;
    }
#pragma unroll
    for (int nt = 0; nt < 4; nt++) {
        float sa = 0.f, sbv = 0.f;
#pragma unroll
        for (int mt = 0; mt < 4; mt++) {
            c[mt][nt][0] = __expf(c[mt][nt][0] - mA[nt]);
            c[mt][nt][2] = __expf(c[mt][nt][2] - mA[nt]);
            c[mt][nt][1] = __expf(c[mt][nt][1] - mB[nt]);
            c[mt][nt][3] = __expf(c[mt][nt][3] - mB[nt]);
            sa  += c[mt][nt][0] + c[mt][nt][2];
            sbv += c[mt][nt][1] + c[mt][nt][3];
        }
        sa  += __shfl_xor_sync(0xffffffffu, sa, 4);
        sa  += __shfl_xor_sync(0xffffffffu, sa, 8);
        sa  += __shfl_xor_sync(0xffffffffu, sa, 16);
        sbv += __shfl_xor_sync(0xffffffffu, sbv, 4);
        sbv += __shfl_xor_sync(0xffffffffu, sbv, 8);
        sbv += __shfl_xor_sync(0xffffffffu, sbv, 16);
        sA[nt] = 1.f / sa; sB[nt] = 1.f / sbv;
    }
    // write w: g_w[t*4096 + i*64 + j], i = 2*bm + wm
    const int ibase = (2 * bm + wm) * 64;
#pragma unroll
    for (int nt = 0; nt < 4; nt++) {
        const int colA = bn * 128 + wn * 32 + nt * 8 + c_lo;
#pragma unroll
        for (int mt = 0; mt < 4; mt++) {
            const int j0 = mt * 16 + r_lo;
            g_w[(size_t)colA * KDIM + ibase + j0]           = c[mt][nt][0] * sA[nt];
            g_w[(size_t)colA * KDIM + ibase + j0 + 8]       = c[mt][nt][2] * sA[nt];
            g_w[(size_t)(colA + 1) * KDIM + ibase + j0]     = c[mt][nt][1] * sB[nt];
            g_w[(size_t)(colA + 1) * KDIM + ibase + j0 + 8] = c[mt][nt][3] * sB[nt];
        }
    }
}

// ---------------------------------------------------------------------------
// Kernel 3: gather partials. Grid (B, 4): block z handles p = z*8 .. z*8+7.
// ---------------------------------------------------------------------------
__global__ __launch_bounds__(256, 4)
void gather_kernel(const float* __restrict__ x,
                   const int* __restrict__ xi) {
    __shared__ float xs[NN * PP];
    __shared__ int   ti[8];
    __shared__ float part[4][NN];

    const int b   = blockIdx.x;
    const int z   = blockIdx.y;
    const int tid = threadIdx.x;

#pragma unroll
    for (int r = 0; r < 8; r++) {
        const int idx = tid + r * 256;
        xs[idx] = x[(size_t)b * (NN * PP) + idx];
    }
    if (tid < 8) ti[tid] = xi[b * PP + z * 8 + tid];
    __syncthreads();

    const int n = tid & 63;
    const int s = tid >> 6;
    float acc = 0.f;
#pragma unroll
    for (int pp = 0; pp < 2; pp++) {
        const int pl = s * 2 + pp;
        const int p  = z * 8 + pl;
        const int t  = ti[pl];
        const float4* row = (const float4*)(g_w + (size_t)t * KDIM + n * 64);
#pragma unroll
        for (int q = 0; q < 16; q++) {
            const float4 v = row[q];
            const int m = q * 4;
            acc += v.x * xs[(m + 0) * 32 + p];
            acc += v.y * xs[(m + 1) * 32 + p];
            acc += v.z * xs[(m + 2) * 32 + p];
            acc += v.w * xs[(m + 3) * 32 + p];
        }
    }
    part[s][n] = acc;
    __syncthreads();
    if (tid < NN) {
        g_Zp[z][b * NN + tid] =
            part[0][tid] + part[1][tid] + part[2][tid] + part[3][tid];
    }
}

__global__ __launch_bounds__(256, 4)
void zfinal_kernel(float* __restrict__ Z) {
    const int i = blockIdx.x * 256 + threadIdx.x;
    Z[i] = g_Zp[0][i] + g_Zp[1][i] + g_Zp[2][i] + g_Zp[3][i];
}

// ---------------------------------------------------------------------------
// Launch. Inputs: x [B,N,P] f32, x_i [B,P] i32, g [4096,4096] f32,
//                 weights [4096,512] f32.  Output: Z (4096 f32) then F.
// ---------------------------------------------------------------------------
extern "C" void kernel_launch(void* const* d_in, const int* in_sizes, int n_in,
                              void* d_out, int out_size) {
    const float* x   = (const float*)d_in[0];
    const int*   xi  = (const int*)d_in[1];
    const float* g   = (const float*)d_in[2];
    const float* wts = (const float*)d_in[3];

    float* Z = (float*)d_out;
    float* F = (float*)d_out + NN * NN;

    cudaFuncSetAttribute(mma_gemm_kernel,
                         cudaFuncAttributeMaxDynamicSharedMemorySize, SMEM_T);

    split_g_kernel<<<dim3(KDIM / 32, KDIM / 128), 256>>>(g);
    split_w_kernel<<<dim3(KDIM / 32, NCOLS / 128), 256>>>(wts);

    mma_gemm_kernel<<<dim3(NCOLS / 128, KDIM / 128), 256, SMEM_T>>>(F);

    gather_kernel<<<dim3(BB, 4), 256>>>(x, xi);
    zfinal_kernel<<<(BB * NN) / 256, 256>>>(Z);
}